// round 16
// baseline (speedup 1.0000x reference)
#include <cuda_runtime.h>

#define E_DIM 8
#define F_DIM 32
#define THREADS 256
#define TILE_M 16
#define MMA_WARPS 8
#define MMA_TILES_PER_WARP 2

using u64 = unsigned long long;

// ---------------- scalar-path constant blob (validated R9/R10) ----------------
struct __align__(16) CBlob {
    float w1[E_DIM * F_DIM];
    float w2[F_DIM * E_DIM];
    float b1[F_DIM];
    float b2[E_DIM];
    float th[E_DIM];
    float pad[4];
};
__constant__ CBlob c_blob;

__global__ void prep_kernel(float* __restrict__ dst_blob,
                            const float* __restrict__ theta,
                            const float* __restrict__ w1,
                            const float* __restrict__ b1,
                            const float* __restrict__ w2,
                            const float* __restrict__ b2)
{
    CBlob* b = (CBlob*)dst_blob;
    const int t = threadIdx.x;                      // 256 threads
    b->w1[t] = w1[t];
    b->w2[t] = w2[t];
    if (t < F_DIM)                    b->b1[t] = b1[t];
    else if (t < F_DIM + E_DIM)       b->b2[t - F_DIM] = b2[t - F_DIM];
    else if (t < F_DIM + 2 * E_DIM)   b->th[t - F_DIM - E_DIM] =
                                          theta[t - F_DIM - E_DIM];
}

// ---------------- packed fp32 helpers ----------------
__device__ __forceinline__ u64 pack2(float lo, float hi) {
    u64 r; asm("mov.b64 %0, {%1, %2};" : "=l"(r) : "f"(lo), "f"(hi)); return r;
}
__device__ __forceinline__ void unpack2(u64 v, float& lo, float& hi) {
    asm("mov.b64 {%0, %1}, %2;" : "=f"(lo), "=f"(hi) : "l"(v));
}
__device__ __forceinline__ u64 fma2(u64 a, u64 b, u64 c) {
    u64 d;
    asm("fma.rn.f32x2 %0, %1, %2, %3;" : "=l"(d) : "l"(a), "l"(b), "l"(c));
    return d;
}

// ---------------- tf32 mma helpers ----------------
__device__ __forceinline__ unsigned f2tf(float f) {
    unsigned r; asm("cvt.rna.tf32.f32 %0, %1;" : "=r"(r) : "f"(f)); return r;
}
__device__ __forceinline__ void mma8(float* c, const unsigned* a, const unsigned* b) {
    asm volatile("mma.sync.aligned.m16n8k8.row.col.f32.tf32.tf32.f32 "
        "{%0,%1,%2,%3}, {%4,%5,%6,%7}, {%8,%9}, {%0,%1,%2,%3};"
        : "+f"(c[0]), "+f"(c[1]), "+f"(c[2]), "+f"(c[3])
        : "r"(a[0]), "r"(a[1]), "r"(a[2]), "r"(a[3]),
          "r"(b[0]), "r"(b[1]));
}

// ---------------- scalar block body (R10-proven, TPT=2) ----------------
__device__ __forceinline__ void scalar_body(long long sblk,
                                            const float* __restrict__ x,
                                            float* __restrict__ out,
                                            long long n_tokens)
{
    const long long token0 = (sblk * THREADS + threadIdx.x) * 2;
    if (token0 + 1 >= n_tokens) return;

    const float4* xp = (const float4*)(x + token0 * E_DIM);
    float4 a0 = xp[0], a1 = xp[1], a2 = xp[2], a3 = xp[3];

    u64 q0[E_DIM], q1[E_DIM];
    {
        float c;
        c = __cosf(a0.x + c_blob.th[0]); q0[0] = pack2(c, c);
        c = __cosf(a0.y + c_blob.th[1]); q0[1] = pack2(c, c);
        c = __cosf(a0.z + c_blob.th[2]); q0[2] = pack2(c, c);
        c = __cosf(a0.w + c_blob.th[3]); q0[3] = pack2(c, c);
        c = __cosf(a1.x + c_blob.th[4]); q0[4] = pack2(c, c);
        c = __cosf(a1.y + c_blob.th[5]); q0[5] = pack2(c, c);
        c = __cosf(a1.z + c_blob.th[6]); q0[6] = pack2(c, c);
        c = __cosf(a1.w + c_blob.th[7]); q0[7] = pack2(c, c);
        c = __cosf(a2.x + c_blob.th[0]); q1[0] = pack2(c, c);
        c = __cosf(a2.y + c_blob.th[1]); q1[1] = pack2(c, c);
        c = __cosf(a2.z + c_blob.th[2]); q1[2] = pack2(c, c);
        c = __cosf(a2.w + c_blob.th[3]); q1[3] = pack2(c, c);
        c = __cosf(a3.x + c_blob.th[4]); q1[4] = pack2(c, c);
        c = __cosf(a3.y + c_blob.th[5]); q1[5] = pack2(c, c);
        c = __cosf(a3.z + c_blob.th[6]); q1[6] = pack2(c, c);
        c = __cosf(a3.w + c_blob.th[7]); q1[7] = pack2(c, c);
    }

    u64 o0[4], o1[4];
    {
        float4 ba = *(const float4*)&c_blob.b2[0];
        float4 bb = *(const float4*)&c_blob.b2[4];
        o0[0] = pack2(ba.x, ba.y); o0[1] = pack2(ba.z, ba.w);
        o0[2] = pack2(bb.x, bb.y); o0[3] = pack2(bb.z, bb.w);
        o1[0] = o0[0]; o1[1] = o0[1]; o1[2] = o0[2]; o1[3] = o0[3];
    }

#pragma unroll
    for (int f4 = 0; f4 < F_DIM / 4; f4++) {
        float4 bb = *(const float4*)&c_blob.b1[f4 * 4];
        u64 hA0 = pack2(bb.x, bb.y), hB0 = pack2(bb.z, bb.w);
        u64 hA1 = hA0, hB1 = hB0;
#pragma unroll
        for (int i = 0; i < E_DIM; i++) {
            float4 w = *(const float4*)&c_blob.w1[i * F_DIM + f4 * 4];
            u64 wA = pack2(w.x, w.y), wB = pack2(w.z, w.w);
            hA0 = fma2(q0[i], wA, hA0);
            hB0 = fma2(q0[i], wB, hB0);
            hA1 = fma2(q1[i], wA, hA1);
            hB1 = fma2(q1[i], wB, hB1);
        }
        float h0[4], h1[4];
        unpack2(hA0, h0[0], h0[1]); unpack2(hB0, h0[2], h0[3]);
        unpack2(hA1, h1[0], h1[1]); unpack2(hB1, h1[2], h1[3]);
#pragma unroll
        for (int j = 0; j < 4; j++) {
            const int f = f4 * 4 + j;
            float d0 = fmaxf(h0[j], 0.0f);
            float d1 = fmaxf(h1[j], 0.0f);
            u64 p0 = pack2(d0, d0), p1 = pack2(d1, d1);
            float4 wa = *(const float4*)&c_blob.w2[f * E_DIM];
            float4 wb = *(const float4*)&c_blob.w2[f * E_DIM + 4];
            u64 w01 = pack2(wa.x, wa.y), w23 = pack2(wa.z, wa.w);
            u64 w45 = pack2(wb.x, wb.y), w67 = pack2(wb.z, wb.w);
            o0[0] = fma2(p0, w01, o0[0]);
            o0[1] = fma2(p0, w23, o0[1]);
            o0[2] = fma2(p0, w45, o0[2]);
            o0[3] = fma2(p0, w67, o0[3]);
            o1[0] = fma2(p1, w01, o1[0]);
            o1[1] = fma2(p1, w23, o1[1]);
            o1[2] = fma2(p1, w45, o1[2]);
            o1[3] = fma2(p1, w67, o1[3]);
        }
    }

    float4 r0, r1, r2, r3;
    unpack2(o0[0], r0.x, r0.y); unpack2(o0[1], r0.z, r0.w);
    unpack2(o0[2], r1.x, r1.y); unpack2(o0[3], r1.z, r1.w);
    unpack2(o1[0], r2.x, r2.y); unpack2(o1[1], r2.z, r2.w);
    unpack2(o1[2], r3.x, r3.y); unpack2(o1[3], r3.z, r3.w);
    float4* op = (float4*)(out + token0 * E_DIM);
    op[0] = r0; op[1] = r1; op[2] = r2; op[3] = r3;
}

// ---------------- mma block body (R15-proven, tile base offset) ----------------
__device__ __forceinline__ void mma_body(long long mblk,
                                         float* hbuf_block,
                                         const float* __restrict__ x,
                                         const float* __restrict__ theta,
                                         const float* __restrict__ w1,
                                         const float* __restrict__ b1,
                                         const float* __restrict__ w2,
                                         const float* __restrict__ b2,
                                         float* __restrict__ out,
                                         long long tile_base,
                                         long long n_tiles)
{
    const int warp = threadIdx.x >> 5;
    const int lane = threadIdx.x & 31;
    const int g    = lane >> 2;
    const int tig  = lane & 3;

    unsigned w1b[4][2], w2b[4][2];
#pragma unroll
    for (int nt = 0; nt < 4; nt++) {
        w1b[nt][0] = f2tf(w1[ tig      * F_DIM + nt * 8 + g]);
        w1b[nt][1] = f2tf(w1[(tig + 4) * F_DIM + nt * 8 + g]);
    }
#pragma unroll
    for (int kc = 0; kc < 4; kc++) {
        w2b[kc][0] = f2tf(w2[(kc * 8 + tig    ) * E_DIM + g]);
        w2b[kc][1] = f2tf(w2[(kc * 8 + tig + 4) * E_DIM + g]);
    }
    float bias1[4][2];
#pragma unroll
    for (int nt = 0; nt < 4; nt++) {
        bias1[nt][0] = b1[nt * 8 + 2 * tig];
        bias1[nt][1] = b1[nt * 8 + 2 * tig + 1];
    }
    const float bz0 = b2[2 * tig], bz1 = b2[2 * tig + 1];
    const float th0 = theta[tig], th1 = theta[tig + 4];

    const int sw = (g & 3) << 3;
    float* hw = hbuf_block + warp * (TILE_M * F_DIM);

    long long tile = tile_base + (mblk * MMA_WARPS + warp) * MMA_TILES_PER_WARP;
#pragma unroll
    for (int tt = 0; tt < MMA_TILES_PER_WARP; tt++, tile++) {
        if (tile >= n_tiles) break;
        const long long tb = tile * TILE_M;
        const float* xr = x + tb * E_DIM;

        unsigned a[4];
        a[0] = f2tf(__cosf(xr[ g      * E_DIM + tig    ] + th0));
        a[1] = f2tf(__cosf(xr[(g + 8) * E_DIM + tig    ] + th0));
        a[2] = f2tf(__cosf(xr[ g      * E_DIM + tig + 4] + th1));
        a[3] = f2tf(__cosf(xr[(g + 8) * E_DIM + tig + 4] + th1));

#pragma unroll
        for (int nt = 0; nt < 4; nt++) {
            float h[4] = {bias1[nt][0], bias1[nt][1],
                          bias1[nt][0], bias1[nt][1]};
            mma8(h, a, w1b[nt]);
            const int c0 = (nt * 8 + 2 * tig) ^ sw;
            *(float2*)&hw[ g      * F_DIM + c0] =
                make_float2(fmaxf(h[0], 0.f), fmaxf(h[1], 0.f));
            *(float2*)&hw[(g + 8) * F_DIM + c0] =
                make_float2(fmaxf(h[2], 0.f), fmaxf(h[3], 0.f));
        }
        __syncwarp();

        float o[4] = {bz0, bz1, bz0, bz1};
#pragma unroll
        for (int kc = 0; kc < 4; kc++) {
            unsigned a2[4];
            const int cA = (kc * 8 + tig    ) ^ sw;
            const int cB = (kc * 8 + tig + 4) ^ sw;
            a2[0] = f2tf(hw[ g      * F_DIM + cA]);
            a2[1] = f2tf(hw[(g + 8) * F_DIM + cA]);
            a2[2] = f2tf(hw[ g      * F_DIM + cB]);
            a2[3] = f2tf(hw[(g + 8) * F_DIM + cB]);
            mma8(o, a2, w2b[kc]);
        }
        __syncwarp();

        float* orow = out + tb * E_DIM;
        *(float2*)&orow[ g      * E_DIM + 2 * tig] = make_float2(o[0], o[1]);
        *(float2*)&orow[(g + 8) * E_DIM + 2 * tig] = make_float2(o[2], o[3]);
    }
}

// ---------------- hybrid dispatch: 1 scalar block per 2 mma blocks ----------------
__global__ void __launch_bounds__(THREADS, 3)
ffq_hybrid(const float* __restrict__ x, const float* __restrict__ theta,
           const float* __restrict__ w1, const float* __restrict__ b1,
           const float* __restrict__ w2, const float* __restrict__ b2,
           float* __restrict__ out,
           long long n_tokens, long long scalar_tokens, long long n_tiles)
{
    __shared__ float hbuf[MMA_WARPS * TILE_M * F_DIM];   // 16 KB (mma blocks)

    const long long bid = blockIdx.x;
    if (bid % 3 == 0) {
        // scalar block: 512 tokens each, region [0, scalar_tokens)
        scalar_body(bid / 3, x, out, scalar_tokens);
    } else {
        // mma block: 256 tokens each, region [scalar_tokens, n_tokens)
        const long long mblk = bid - bid / 3 - 1;
        mma_body(mblk, hbuf, x, theta, w1, b1, w2, b2, out,
                 scalar_tokens / TILE_M, n_tiles);
    }
    (void)n_tokens;
}

extern "C" void kernel_launch(void* const* d_in, const int* in_sizes, int n_in,
                              void* d_out, int out_size) {
    const float* x     = (const float*)d_in[0];
    const float* theta = (const float*)d_in[1];
    const float* w1    = (const float*)d_in[2];
    const float* b1    = (const float*)d_in[3];
    const float* w2    = (const float*)d_in[4];
    const float* b2    = (const float*)d_in[5];
    float* out         = (float*)d_out;

    void* blob_dev = nullptr;
    (void)cudaGetSymbolAddress(&blob_dev, c_blob);
    prep_kernel<<<1, THREADS>>>((float*)blob_dev, theta, w1, b1, w2, b2);

    const long long n_tokens = (long long)in_sizes[0] / E_DIM;   // 524288
    // Per 3-block group: 1 scalar block (512 tok) + 2 mma blocks (512 tok).
    const long long groups        = n_tokens / 1024;             // 512
    const long long scalar_tokens = groups * 512;                // 262144
    const long long n_tiles       = n_tokens / TILE_M;           // 32768
    const int blocks              = (int)(groups * 3);           // 1536

    ffq_hybrid<<<blocks, THREADS>>>(x, theta, w1, b1, w2, b2, out,
                                    n_tokens, scalar_tokens, n_tiles);
}

// round 17
// speedup vs baseline: 1.2792x; 1.2792x over previous
#include <cuda_runtime.h>

#define THREADS 256
#define WARPS_PER_BLOCK 8
#define TILES_PER_WARP 2
#define TILE_M 16
#define E_DIM 8
#define F_DIM 32

// f32 -> tf32 (round-to-nearest)
__device__ __forceinline__ unsigned f2tf(float f) {
    unsigned r; asm("cvt.rna.tf32.f32 %0, %1;" : "=r"(r) : "f"(f)); return r;
}
// m16n8k8 tf32 MMA, D = A*B + D
__device__ __forceinline__ void mma8(float* c, const unsigned* a, const unsigned* b) {
    asm volatile("mma.sync.aligned.m16n8k8.row.col.f32.tf32.tf32.f32 "
        "{%0,%1,%2,%3}, {%4,%5,%6,%7}, {%8,%9}, {%0,%1,%2,%3};"
        : "+f"(c[0]), "+f"(c[1]), "+f"(c[2]), "+f"(c[3])
        : "r"(a[0]), "r"(a[1]), "r"(a[2]), "r"(a[3]),
          "r"(b[0]), "r"(b[1]));
}

__global__ void __launch_bounds__(THREADS, 4)
ffq_kernel(const float* __restrict__ x, const float* __restrict__ theta,
           const float* __restrict__ w1, const float* __restrict__ b1,
           const float* __restrict__ w2, const float* __restrict__ b2,
           float* __restrict__ out, long long n_tiles)
{
    // Per-warp h buffer in GEMM2 A-FRAGMENT ORDER:
    //   entry (kc, t, slot) = { h[g][8kc+t], h[g+8][8kc+t],
    //                           h[g][8kc+t+4], h[g+8][8kc+t+4] },  g = slot ^ 2t
    // Stores (2x float2 per nt) and loads (1x float4 per kc) are both
    // bank-conflict-free (verified per 16/8-lane phase).
    __shared__ float4 hbuf[WARPS_PER_BLOCK][128];   // 2 KB/warp, 16 KB/block

    const int warp = threadIdx.x >> 5;
    const int lane = threadIdx.x & 31;
    const int g    = lane >> 2;    // row-group 0..7
    const int tig  = lane & 3;     // thread-in-group 0..3

    // ---- loop-invariant fragments ----
    unsigned w1b[4][2], w2b[4][2];
#pragma unroll
    for (int nt = 0; nt < 4; nt++) {
        w1b[nt][0] = f2tf(w1[ tig      * F_DIM + nt * 8 + g]);
        w1b[nt][1] = f2tf(w1[(tig + 4) * F_DIM + nt * 8 + g]);
    }
#pragma unroll
    for (int kc = 0; kc < 4; kc++) {
        w2b[kc][0] = f2tf(w2[(kc * 8 + tig    ) * E_DIM + g]);
        w2b[kc][1] = f2tf(w2[(kc * 8 + tig + 4) * E_DIM + g]);
    }
    float bias1[4][2];
#pragma unroll
    for (int nt = 0; nt < 4; nt++) {
        bias1[nt][0] = b1[nt * 8 + 2 * tig];
        bias1[nt][1] = b1[nt * 8 + 2 * tig + 1];
    }
    const float bz0 = b2[2 * tig], bz1 = b2[2 * tig + 1];
    const float th0 = theta[tig], th1 = theta[tig + 4];

    float* hw = (float*)hbuf[warp];

    // store slots for this thread's two C-fragment columns (w = 2tig, 2tig+1)
    const int wc0 = 2 * tig,      wc1 = 2 * tig + 1;
    const int t0  = wc0 & 3,      t1  = wc1 & 3;
    const int cp0 = (wc0 & 4) >> 1, cp1 = (wc1 & 4) >> 1;     // 0 or 2
    const int sl0 = g ^ (t0 << 1), sl1 = g ^ (t1 << 1);
    const int ldslot = g ^ (tig << 1);

    long long tile = ((long long)blockIdx.x * WARPS_PER_BLOCK + warp)
                     * TILES_PER_WARP;
#pragma unroll
    for (int tt = 0; tt < TILES_PER_WARP; tt++, tile++) {
        if (tile >= n_tiles) break;
        const long long tb = tile * TILE_M;
        const float* xr = x + tb * E_DIM;

        // ---- A fragment for GEMM1: q = cos(x + theta) ----
        unsigned a[4];
        a[0] = f2tf(__cosf(xr[ g      * E_DIM + tig    ] + th0));
        a[1] = f2tf(__cosf(xr[(g + 8) * E_DIM + tig    ] + th0));
        a[2] = f2tf(__cosf(xr[ g      * E_DIM + tig + 4] + th1));
        a[3] = f2tf(__cosf(xr[(g + 8) * E_DIM + tig + 4] + th1));

        // ---- GEMM1 (4 n-tiles) + relu -> fragment-order smem ----
#pragma unroll
        for (int nt = 0; nt < 4; nt++) {
            float h[4] = {bias1[nt][0], bias1[nt][1],
                          bias1[nt][0], bias1[nt][1]};
            mma8(h, a, w1b[nt]);
            // column wc0: rows g, g+8  -> entry (nt, t0, sl0), comps cp0..cp0+1
            *(float2*)&hw[((nt * 4 + t0) * 8 + sl0) * 4 + cp0] =
                make_float2(fmaxf(h[0], 0.f), fmaxf(h[2], 0.f));
            // column wc1
            *(float2*)&hw[((nt * 4 + t1) * 8 + sl1) * 4 + cp1] =
                make_float2(fmaxf(h[1], 0.f), fmaxf(h[3], 0.f));
        }
        __syncwarp();

        // ---- GEMM2: one LDS.128 per k-chunk, fragment-ready ----
        float o[4] = {bz0, bz1, bz0, bz1};
#pragma unroll
        for (int kc = 0; kc < 4; kc++) {
            float4 v = hbuf[warp][(kc * 4 + tig) * 8 + ldslot];
            unsigned a2[4] = {f2tf(v.x), f2tf(v.y), f2tf(v.z), f2tf(v.w)};
            mma8(o, a2, w2b[kc]);
        }
        __syncwarp();   // loads complete before next tile overwrites hw

        // ---- store: (g, 2tig..2tig+1) and (g+8, ...) ----
        float* orow = out + tb * E_DIM;
        *(float2*)&orow[ g      * E_DIM + 2 * tig] = make_float2(o[0], o[1]);
        *(float2*)&orow[(g + 8) * E_DIM + 2 * tig] = make_float2(o[2], o[3]);
    }
}

extern "C" void kernel_launch(void* const* d_in, const int* in_sizes, int n_in,
                              void* d_out, int out_size) {
    const float* x     = (const float*)d_in[0];
    const float* theta = (const float*)d_in[1];
    const float* w1    = (const float*)d_in[2];
    const float* b1    = (const float*)d_in[3];
    const float* w2    = (const float*)d_in[4];
    const float* b2    = (const float*)d_in[5];
    float* out         = (float*)d_out;

    const long long n_tokens = (long long)in_sizes[0] / E_DIM;   // B*S
    const long long n_tiles  = n_tokens / TILE_M;                // 32768
    const long long per_blk  = (long long)WARPS_PER_BLOCK * TILES_PER_WARP;
    const int blocks         = (int)((n_tiles + per_blk - 1) / per_blk);

    // Single graph node.
    ffq_kernel<<<blocks, THREADS>>>(x, theta, w1, b1, w2, b2, out, n_tiles);
}